// round 14
// baseline (speedup 1.0000x reference)
#include <cuda_runtime.h>

typedef unsigned long long ull;

#define BS 2
#define NN 2048
#define DIN 128
#define DOUT 128
#define H 8
#define DK 16

// -------- scratch (no allocs allowed) --------
__device__ float g_Q[(size_t)BS*H*NN*DK];   // row-major [bh][n][d]
__device__ float g_K[(size_t)BS*H*NN*DK];   // TRANSPOSED [bh][d][m]
__device__ float g_V[(size_t)BS*H*NN*DK];   // TRANSPOSED [bh][d][m]

// ---------- f32x2 helpers ----------
__device__ __forceinline__ void ffma2(ull& d, ull a, ull b) {
    asm("fma.rn.f32x2 %0, %1, %2, %0;" : "+l"(d) : "l"(a), "l"(b));
}
__device__ __forceinline__ ull pk2(float a, float b) {
    ull r; asm("mov.b64 %0, {%1, %2};" : "=l"(r) : "f"(a), "f"(b)); return r;
}
__device__ __forceinline__ float2 upk(ull v) {
    float2 r; asm("mov.b64 {%0, %1}, %2;" : "=f"(r.x), "=f"(r.y) : "l"(v)); return r;
}

// ============================================================
// Projection: y = X @ W^T + b
// Q -> [bh][n][d];  K,V -> transposed [bh][d][n]
// ============================================================
#define PBM 64
__global__ __launch_bounds__(256, 2) void proj_kernel(
    const float* __restrict__ X,
    const float* __restrict__ Wq, const float* __restrict__ bq,
    const float* __restrict__ Wk, const float* __restrict__ bk,
    const float* __restrict__ Wv, const float* __restrict__ bv)
{
    __shared__ float Xs[PBM][33];
    __shared__ float Wt[32][128];

    int tid = threadIdx.x;
    int sel = blockIdx.y;
    const float* W    = (sel == 0) ? Wq : ((sel == 1) ? Wk : Wv);
    const float* bias = (sel == 0) ? bq : ((sel == 1) ? bk : bv);
    float* dst        = (sel == 0) ? g_Q : ((sel == 1) ? g_K : g_V);

    int tx = tid & 63;
    int ty = tid >> 6;
    int row0 = blockIdx.x * PBM;

    float acc0[16], acc1[16];
#pragma unroll
    for (int i = 0; i < 16; i++) { acc0[i] = 0.f; acc1[i] = 0.f; }

    for (int k0 = 0; k0 < DIN; k0 += 32) {
        __syncthreads();
#pragma unroll
        for (int r = 0; r < 2; r++) {
            int i = tid + 256 * r;
            int xr = i >> 3;
            int xc = (i & 7) << 2;
            float4 xv = *(const float4*)(X + (size_t)(row0 + xr) * DIN + k0 + xc);
            Xs[xr][xc + 0] = xv.x; Xs[xr][xc + 1] = xv.y;
            Xs[xr][xc + 2] = xv.z; Xs[xr][xc + 3] = xv.w;
        }
#pragma unroll
        for (int r = 0; r < 4; r++) {
            int i = tid + 256 * r;
            int o  = i >> 3;
            int kc = (i & 7) << 2;
            float4 wv = *(const float4*)(W + (size_t)o * DIN + k0 + kc);
            Wt[kc + 0][o] = wv.x; Wt[kc + 1][o] = wv.y;
            Wt[kc + 2][o] = wv.z; Wt[kc + 3][o] = wv.w;
        }
        __syncthreads();
#pragma unroll
        for (int kk = 0; kk < 32; kk++) {
            float w0 = Wt[kk][tx];
            float w1 = Wt[kk][tx + 64];
#pragma unroll
            for (int rr = 0; rr < 16; rr++) {
                float xv = Xs[ty * 16 + rr][kk];
                acc0[rr] = fmaf(xv, w0, acc0[rr]);
                acc1[rr] = fmaf(xv, w1, acc1[rr]);
            }
        }
    }

    float b0 = bias[tx], b1 = bias[tx + 64];
    int c0 = tx, c1 = tx + 64;
    int grow0 = row0 + ty * 16;
    int bidx = grow0 / NN;
    int nb = grow0 % NN;         // multiple of 16

    if (sel == 0) {
#pragma unroll
        for (int rr = 0; rr < 16; rr++) {
            int n = nb + rr;
            dst[(((size_t)bidx * H + (c0 >> 4)) * NN + n) * DK + (c0 & 15)] = acc0[rr] + b0;
            dst[(((size_t)bidx * H + (c1 >> 4)) * NN + n) * DK + (c1 & 15)] = acc1[rr] + b1;
        }
    } else {
        // transposed [bh][d][n]: each thread owns 16 consecutive n
        float* p0 = dst + (((size_t)bidx * H + (c0 >> 4)) * DK + (c0 & 15)) * NN + nb;
        float* p1 = dst + (((size_t)bidx * H + (c1 >> 4)) * DK + (c1 & 15)) * NN + nb;
#pragma unroll
        for (int rq = 0; rq < 4; rq++) {
            *(float4*)(p0 + 4 * rq) = make_float4(acc0[4*rq+0] + b0, acc0[4*rq+1] + b0,
                                                  acc0[4*rq+2] + b0, acc0[4*rq+3] + b0);
            *(float4*)(p1 + 4 * rq) = make_float4(acc1[4*rq+0] + b1, acc1[4*rq+1] + b1,
                                                  acc1[4*rq+2] + b1, acc1[4*rq+3] + b1);
        }
    }
}

// ============================================================
// Fused attention, 2 rows/warp, ZERO shared memory, ZERO barriers:
// K/V transposed in gmem; the m-pair ulonglong2 loads are coalesced
// LDG.128 from L1 (same wavefront cost as the LDS they replace).
// Pass 1: QK (f32x2 m-packed) + bias + mask -> RAW scores, online stats.
// Pass 2: LDG raw scores, p = exp(s-mx)*inv, overwrite p, packed PV.
// grid (128,8,2), block 256.
// ============================================================
#define ROWS_PB 16
#define NCH (NN / 128)      // 16 chunks of 128 keys

__global__ __launch_bounds__(256, 2) void attn_kernel(
    const float* __restrict__ sp, const int* __restrict__ adj,
    float* __restrict__ outp, float* __restrict__ scorep)
{
    int tid = threadIdx.x;
    int w = tid >> 5;
    int l = tid & 31;
    int h = blockIdx.y, b = blockIdx.z;
    int bh = b * H + h;
    int n0 = blockIdx.x * ROWS_PB + w * 2;
    int n1 = n0 + 1;

    const float* kt = g_K + (size_t)bh * DK * NN;   // [d][m]
    const float* vt = g_V + (size_t)bh * DK * NN;   // [d][m]

    size_t ar0 = ((size_t)bh * NN + n0) * NN;
    size_t ar1 = ((size_t)bh * NN + n1) * NN;

    // q dup packs (q[d], q[d]) pre-scaled by 1/sqrt(DK)=0.25
    ull qq0[DK], qq1[DK];
    {
        const float* qr0 = g_Q + ((size_t)bh * NN + n0) * DK;
        const float* qr1 = g_Q + ((size_t)bh * NN + n1) * DK;
#pragma unroll
        for (int d = 0; d < DK; d++) {
            float v0 = qr0[d] * 0.25f;
            float v1 = qr1[d] * 0.25f;
            qq0[d] = pk2(v0, v0);
            qq1[d] = pk2(v1, v1);
        }
    }

    const float* sp0 = sp + (size_t)n0 * NN;
    const float* sp1 = sp + (size_t)n1 * NN;
    const int* ad0 = adj + ((size_t)b * NN + n0) * NN;
    const int* ad1 = adj + ((size_t)b * NN + n1) * NN;

    float mx0 = -3.0e38f, mx1 = -3.0e38f, S0 = 0.f, S1 = 0.f;

    // ================= Pass 1: scores + stats =================
#pragma unroll 2
    for (int c = 0; c < NCH; c++) {
        int mg = c * 128 + 4 * l;

        ull d0a = 0ull, d0b = 0ull, d1a = 0ull, d1b = 0ull;
#pragma unroll
        for (int d = 0; d < DK; d++) {
            ulonglong2 kk = *(const ulonglong2*)(kt + (size_t)d * NN + mg);
            ffma2(d0a, qq0[d], kk.x); ffma2(d0b, qq0[d], kk.y);
            ffma2(d1a, qq1[d], kk.x); ffma2(d1b, qq1[d], kk.y);
        }
        float2 u0a = upk(d0a), u0b = upk(d0b), u1a = upk(d1a), u1b = upk(d1b);

        float4 sv0 = *(const float4*)(sp0 + mg);
        float4 sv1 = *(const float4*)(sp1 + mg);
        int4 a0 = *(const int4*)(ad0 + mg);
        int4 a1 = *(const int4*)(ad1 + mg);

        sv0.x = (mg + 0 == n0) ? 0.f : sv0.x;
        sv0.y = (mg + 1 == n0) ? 0.f : sv0.y;
        sv0.z = (mg + 2 == n0) ? 0.f : sv0.z;
        sv0.w = (mg + 3 == n0) ? 0.f : sv0.w;
        sv1.x = (mg + 0 == n1) ? 0.f : sv1.x;
        sv1.y = (mg + 1 == n1) ? 0.f : sv1.y;
        sv1.z = (mg + 2 == n1) ? 0.f : sv1.z;
        sv1.w = (mg + 3 == n1) ? 0.f : sv1.w;

        float s00 = a0.x ? (u0a.x + sv0.x) : -1e10f;
        float s01 = a0.y ? (u0a.y + sv0.y) : -1e10f;
        float s02 = a0.z ? (u0b.x + sv0.z) : -1e10f;
        float s03 = a0.w ? (u0b.y + sv0.w) : -1e10f;
        float s10 = a1.x ? (u1a.x + sv1.x) : -1e10f;
        float s11 = a1.y ? (u1a.y + sv1.y) : -1e10f;
        float s12 = a1.z ? (u1b.x + sv1.z) : -1e10f;
        float s13 = a1.w ? (u1b.y + sv1.w) : -1e10f;

        // raw scores out (re-read in pass 2 by this same thread)
        *(float4*)(scorep + ar0 + mg) = make_float4(s00, s01, s02, s03);
        *(float4*)(scorep + ar1 + mg) = make_float4(s10, s11, s12, s13);

        float cm0 = fmaxf(fmaxf(s00, s01), fmaxf(s02, s03));
        float nm0 = fmaxf(mx0, cm0);
        S0 = S0 * __expf(mx0 - nm0)
           + __expf(s00 - nm0) + __expf(s01 - nm0)
           + __expf(s02 - nm0) + __expf(s03 - nm0);
        mx0 = nm0;

        float cm1 = fmaxf(fmaxf(s10, s11), fmaxf(s12, s13));
        float nm1 = fmaxf(mx1, cm1);
        S1 = S1 * __expf(mx1 - nm1)
           + __expf(s10 - nm1) + __expf(s11 - nm1)
           + __expf(s12 - nm1) + __expf(s13 - nm1);
        mx1 = nm1;
    }

    // warp-combine (max,sum) exactly
#pragma unroll
    for (int off = 16; off; off >>= 1) {
        float mo = __shfl_xor_sync(0xffffffffu, mx0, off);
        float so = __shfl_xor_sync(0xffffffffu, S0, off);
        float nm = fmaxf(mx0, mo);
        S0 = S0 * __expf(mx0 - nm) + so * __expf(mo - nm);
        mx0 = nm;
        mo = __shfl_xor_sync(0xffffffffu, mx1, off);
        so = __shfl_xor_sync(0xffffffffu, S1, off);
        nm = fmaxf(mx1, mo);
        S1 = S1 * __expf(mx1 - nm) + so * __expf(mo - nm);
        mx1 = nm;
    }
    float inv0 = 1.f / S0, inv1 = 1.f / S1;

    // ================= Pass 2: normalize + PV (packed even/odd) =========
    ull op0[DK], op1[DK];
#pragma unroll
    for (int d = 0; d < DK; d++) { op0[d] = 0ull; op1[d] = 0ull; }

#pragma unroll 2
    for (int c = 0; c < NCH; c++) {
        int mg = c * 128 + 4 * l;

        float4 r0 = *(const float4*)(scorep + ar0 + mg);
        float4 r1 = *(const float4*)(scorep + ar1 + mg);

        float p00 = __expf(r0.x - mx0) * inv0;
        float p01 = __expf(r0.y - mx0) * inv0;
        float p02 = __expf(r0.z - mx0) * inv0;
        float p03 = __expf(r0.w - mx0) * inv0;
        float p10 = __expf(r1.x - mx1) * inv1;
        float p11 = __expf(r1.y - mx1) * inv1;
        float p12 = __expf(r1.z - mx1) * inv1;
        float p13 = __expf(r1.w - mx1) * inv1;

        *(float4*)(scorep + ar0 + mg) = make_float4(p00, p01, p02, p03);
        *(float4*)(scorep + ar1 + mg) = make_float4(p10, p11, p12, p13);

        ull pe0 = pk2(p00, p01), po0 = pk2(p02, p03);
        ull pe1 = pk2(p10, p11), po1 = pk2(p12, p13);

#pragma unroll
        for (int d = 0; d < DK; d++) {
            ulonglong2 kk = *(const ulonglong2*)(vt + (size_t)d * NN + mg);
            ffma2(op0[d], pe0, kk.x); ffma2(op0[d], po0, kk.y);
            ffma2(op1[d], pe1, kk.x); ffma2(op1[d], po1, kk.y);
        }
    }

    // collapse even/odd halves, then butterfly reduce across lanes
    float o0[DK], o1[DK];
#pragma unroll
    for (int d = 0; d < DK; d++) {
        float2 e0 = upk(op0[d]); o0[d] = e0.x + e0.y;
        float2 e1 = upk(op1[d]); o1[d] = e1.x + e1.y;
    }
#pragma unroll
    for (int off = 16; off; off >>= 1) {
#pragma unroll
        for (int d = 0; d < DK; d++) {
            o0[d] += __shfl_xor_sync(0xffffffffu, o0[d], off);
            o1[d] += __shfl_xor_sync(0xffffffffu, o1[d], off);
        }
    }

    // out layout: out[(b*N+n)*128 + d*8 + h]
    if (outp) {
        if (l == 0) {
            float* ob = outp + ((size_t)b * NN + n0) * DOUT + h;
#pragma unroll
            for (int d = 0; d < DK; d++) ob[(size_t)d * H] = o0[d];
        } else if (l == 1) {
            float* ob = outp + ((size_t)b * NN + n1) * DOUT + h;
#pragma unroll
            for (int d = 0; d < DK; d++) ob[(size_t)d * H] = o1[d];
        }
    }
}

// ============================================================
extern "C" void kernel_launch(void* const* d_in, const int* in_sizes, int n_in,
                              void* d_out, int out_size) {
    const float* x   = (const float*)d_in[0];
    const int*   adj = (const int*)  d_in[1];
    const float* sp  = (const float*)d_in[2];
    const float* Wq  = (const float*)d_in[3];
    const float* bq  = (const float*)d_in[4];
    const float* Wk  = (const float*)d_in[5];
    const float* bk  = (const float*)d_in[6];
    const float* Wv  = (const float*)d_in[7];
    const float* bv  = (const float*)d_in[8];

    const long long OUT_ELEMS  = (long long)BS * NN * DOUT;              // 524288
    const long long ATTN_ELEMS = (long long)BS * H * NN * (long long)NN; // 67108864

    float* base  = (float*)d_out;
    float* outp  = nullptr;
    float* attnp = nullptr;
    long long osz = (long long)out_size;
    if (osz >= OUT_ELEMS + ATTN_ELEMS) { outp = base; attnp = base + OUT_ELEMS; }
    else if (osz == ATTN_ELEMS)        { attnp = base; }
    else                               { outp = base; }

    float* scorep = attnp ? attnp : base;

    dim3 pgrid(BS * NN / PBM, 3);
    proj_kernel<<<pgrid, 256>>>(x, Wq, bq, Wk, bk, Wv, bv);

    dim3 agrid(NN / ROWS_PB, H, BS);
    attn_kernel<<<agrid, 256>>>(sp, adj, outp, scorep);
}

// round 15
// speedup vs baseline: 1.2118x; 1.2118x over previous
#include <cuda_runtime.h>

typedef unsigned long long ull;

#define BS 2
#define NN 2048
#define DIN 128
#define DOUT 128
#define H 8
#define DK 16

#define TMA 256
#define NT (NN / TMA)       // 8 tiles
#define STRD (TMA + 4)      // transposed [d][m] rows, conflict-free LDS.128

// -------- scratch (no allocs allowed) --------
__device__ float g_Q[(size_t)BS*H*NN*DK];
__device__ float g_K[(size_t)BS*H*NN*DK];
__device__ float g_V[(size_t)BS*H*NN*DK];

// ---------- f32x2 helpers ----------
__device__ __forceinline__ void ffma2(ull& d, ull a, ull b) {
    asm("fma.rn.f32x2 %0, %1, %2, %0;" : "+l"(d) : "l"(a), "l"(b));
}
__device__ __forceinline__ ull pk2(float a, float b) {
    ull r; asm("mov.b64 %0, {%1, %2};" : "=l"(r) : "f"(a), "f"(b)); return r;
}
__device__ __forceinline__ float2 upk(ull v) {
    float2 r; asm("mov.b64 {%0, %1}, %2;" : "=f"(r.x), "=f"(r.y) : "l"(v)); return r;
}

// ============================================================
// Projection: y = X @ W^T + b, written as [b][h][n][dk]
// ============================================================
#define PBM 64
__global__ __launch_bounds__(256, 2) void proj_kernel(
    const float* __restrict__ X,
    const float* __restrict__ Wq, const float* __restrict__ bq,
    const float* __restrict__ Wk, const float* __restrict__ bk,
    const float* __restrict__ Wv, const float* __restrict__ bv)
{
    __shared__ float Xs[PBM][33];
    __shared__ float Wt[32][128];

    int tid = threadIdx.x;
    int sel = blockIdx.y;
    const float* W    = (sel == 0) ? Wq : ((sel == 1) ? Wk : Wv);
    const float* bias = (sel == 0) ? bq : ((sel == 1) ? bk : bv);
    float* dst        = (sel == 0) ? g_Q : ((sel == 1) ? g_K : g_V);

    int tx = tid & 63;
    int ty = tid >> 6;
    int row0 = blockIdx.x * PBM;

    float acc0[16], acc1[16];
#pragma unroll
    for (int i = 0; i < 16; i++) { acc0[i] = 0.f; acc1[i] = 0.f; }

    for (int k0 = 0; k0 < DIN; k0 += 32) {
        __syncthreads();
#pragma unroll
        for (int r = 0; r < 2; r++) {
            int i = tid + 256 * r;
            int xr = i >> 3;
            int xc = (i & 7) << 2;
            float4 xv = *(const float4*)(X + (size_t)(row0 + xr) * DIN + k0 + xc);
            Xs[xr][xc + 0] = xv.x; Xs[xr][xc + 1] = xv.y;
            Xs[xr][xc + 2] = xv.z; Xs[xr][xc + 3] = xv.w;
        }
#pragma unroll
        for (int r = 0; r < 4; r++) {
            int i = tid + 256 * r;
            int o  = i >> 3;
            int kc = (i & 7) << 2;
            float4 wv = *(const float4*)(W + (size_t)o * DIN + k0 + kc);
            Wt[kc + 0][o] = wv.x; Wt[kc + 1][o] = wv.y;
            Wt[kc + 2][o] = wv.z; Wt[kc + 3][o] = wv.w;
        }
        __syncthreads();
#pragma unroll
        for (int kk = 0; kk < 32; kk++) {
            float w0 = Wt[kk][tx];
            float w1 = Wt[kk][tx + 64];
#pragma unroll
            for (int rr = 0; rr < 16; rr++) {
                float xv = Xs[ty * 16 + rr][kk];
                acc0[rr] = fmaf(xv, w0, acc0[rr]);
                acc1[rr] = fmaf(xv, w1, acc1[rr]);
            }
        }
    }

    float b0 = bias[tx], b1 = bias[tx + 64];
    int c0 = tx, c1 = tx + 64;
#pragma unroll
    for (int rr = 0; rr < 16; rr++) {
        int grow = row0 + ty * 16 + rr;
        int b = grow / NN, n = grow % NN;
        dst[(((size_t)b * H + (c0 >> 4)) * NN + n) * DK + (c0 & 15)] = acc0[rr] + b0;
        dst[(((size_t)b * H + (c1 >> 4)) * NN + n) * DK + (c1 & 15)] = acc1[rr] + b1;
    }
}

// ============================================================
// Fused attention (R6 structure, double-buffered tiles):
// Pass 1: QK (f32x2 m-packed) + bias + mask -> RAW scores, online stats.
// Pass 2: LDG raw scores, p = exp(s-mx)*inv, overwrite p, packed PV.
// Double buffer: prefetch tile t+1 (LDG) before compute of t, STS after,
// ONE __syncthreads per tile. grid (128,8,2), block 256.
// ============================================================
#define ROWS_PB 16

__global__ __launch_bounds__(256, 2) void attn_kernel(
    const float* __restrict__ sp, const int* __restrict__ adj,
    float* __restrict__ outp, float* __restrict__ scorep)
{
    __shared__ float ts[2][DK][STRD];   // double-buffered transposed tiles

    int tid = threadIdx.x;
    int w = tid >> 5;
    int l = tid & 31;
    int h = blockIdx.y, b = blockIdx.z;
    int bh = b * H + h;
    int n0 = blockIdx.x * ROWS_PB + w * 2;
    int n1 = n0 + 1;

    const float* kb = g_K + (size_t)bh * NN * DK;
    const float* vb = g_V + (size_t)bh * NN * DK;

    size_t ar0 = ((size_t)bh * NN + n0) * NN;
    size_t ar1 = ((size_t)bh * NN + n1) * NN;

    // staging indices (constant per thread)
    int sm0 = tid >> 2;                 // m for r=0 chunk
    int sdg = (tid & 3) << 2;           // d-group

    // q dup packs (q[d], q[d]) pre-scaled by 1/sqrt(DK)=0.25
    ull qq0[DK], qq1[DK];
    {
        const float* qr0 = g_Q + ((size_t)bh * NN + n0) * DK;
        const float* qr1 = g_Q + ((size_t)bh * NN + n1) * DK;
#pragma unroll
        for (int d = 0; d < DK; d++) {
            float v0 = qr0[d] * 0.25f;
            float v1 = qr1[d] * 0.25f;
            qq0[d] = pk2(v0, v0);
            qq1[d] = pk2(v1, v1);
        }
    }

    const float* sp0 = sp + (size_t)n0 * NN;
    const float* sp1 = sp + (size_t)n1 * NN;
    const int* ad0 = adj + ((size_t)b * NN + n0) * NN;
    const int* ad1 = adj + ((size_t)b * NN + n1) * NN;

    float mx0 = -3.0e38f, mx1 = -3.0e38f, S0 = 0.f, S1 = 0.f;

    // ---- staging helpers (4 float4 per thread per tile) ----
#define LOADT(pf, srcbase, t)                                               \
    _Pragma("unroll")                                                       \
    for (int r = 0; r < 4; r++)                                             \
        pf[r] = *(const float4*)((srcbase) +                                \
                 ((size_t)((t) * TMA + sm0 + 64 * r)) * DK + sdg);

#define STORET(pf, bb)                                                      \
    _Pragma("unroll")                                                       \
    for (int r = 0; r < 4; r++) {                                           \
        int m = sm0 + 64 * r;                                               \
        ts[bb][sdg + 0][m] = pf[r].x; ts[bb][sdg + 1][m] = pf[r].y;         \
        ts[bb][sdg + 2][m] = pf[r].z; ts[bb][sdg + 3][m] = pf[r].w;         \
    }

    // ================= Pass 1: scores + stats =================
    {
        float4 pf[4];
        LOADT(pf, kb, 0);
        STORET(pf, 0);
        __syncthreads();
    }
    for (int t = 0; t < NT; t++) {
        float4 pf[4];
        if (t + 1 < NT) { LOADT(pf, kb, t + 1); }
        int bb = t & 1;

#pragma unroll
        for (int c = 0; c < 2; c++) {
            int mm = c * 128 + 4 * l;
            int mg = t * TMA + mm;

            ull d0a = 0ull, d0b = 0ull, d1a = 0ull, d1b = 0ull;
#pragma unroll
            for (int d = 0; d < DK; d++) {
                ulonglong2 kk = *(const ulonglong2*)&ts[bb][d][mm];
                ffma2(d0a, qq0[d], kk.x); ffma2(d0b, qq0[d], kk.y);
                ffma2(d1a, qq1[d], kk.x); ffma2(d1b, qq1[d], kk.y);
            }
            float2 u0a = upk(d0a), u0b = upk(d0b), u1a = upk(d1a), u1b = upk(d1b);

            float4 sv0 = *(const float4*)(sp0 + mg);
            float4 sv1 = *(const float4*)(sp1 + mg);
            int4 a0 = *(const int4*)(ad0 + mg);
            int4 a1 = *(const int4*)(ad1 + mg);

            sv0.x = (mg + 0 == n0) ? 0.f : sv0.x;
            sv0.y = (mg + 1 == n0) ? 0.f : sv0.y;
            sv0.z = (mg + 2 == n0) ? 0.f : sv0.z;
            sv0.w = (mg + 3 == n0) ? 0.f : sv0.w;
            sv1.x = (mg + 0 == n1) ? 0.f : sv1.x;
            sv1.y = (mg + 1 == n1) ? 0.f : sv1.y;
            sv1.z = (mg + 2 == n1) ? 0.f : sv1.z;
            sv1.w = (mg + 3 == n1) ? 0.f : sv1.w;

            float s00 = a0.x ? (u0a.x + sv0.x) : -1e10f;
            float s01 = a0.y ? (u0a.y + sv0.y) : -1e10f;
            float s02 = a0.z ? (u0b.x + sv0.z) : -1e10f;
            float s03 = a0.w ? (u0b.y + sv0.w) : -1e10f;
            float s10 = a1.x ? (u1a.x + sv1.x) : -1e10f;
            float s11 = a1.y ? (u1a.y + sv1.y) : -1e10f;
            float s12 = a1.z ? (u1b.x + sv1.z) : -1e10f;
            float s13 = a1.w ? (u1b.y + sv1.w) : -1e10f;

            *(float4*)(scorep + ar0 + mg) = make_float4(s00, s01, s02, s03);
            *(float4*)(scorep + ar1 + mg) = make_float4(s10, s11, s12, s13);

            float cm0 = fmaxf(fmaxf(s00, s01), fmaxf(s02, s03));
            float nm0 = fmaxf(mx0, cm0);
            S0 = S0 * __expf(mx0 - nm0)
               + __expf(s00 - nm0) + __expf(s01 - nm0)
               + __expf(s02 - nm0) + __expf(s03 - nm0);
            mx0 = nm0;

            float cm1 = fmaxf(fmaxf(s10, s11), fmaxf(s12, s13));
            float nm1 = fmaxf(mx1, cm1);
            S1 = S1 * __expf(mx1 - nm1)
               + __expf(s10 - nm1) + __expf(s11 - nm1)
               + __expf(s12 - nm1) + __expf(s13 - nm1);
            mx1 = nm1;
        }

        if (t + 1 < NT) { STORET(pf, bb ^ 1); }
        __syncthreads();
    }

    // warp-combine (max,sum) exactly
#pragma unroll
    for (int off = 16; off; off >>= 1) {
        float mo = __shfl_xor_sync(0xffffffffu, mx0, off);
        float so = __shfl_xor_sync(0xffffffffu, S0, off);
        float nm = fmaxf(mx0, mo);
        S0 = S0 * __expf(mx0 - nm) + so * __expf(mo - nm);
        mx0 = nm;
        mo = __shfl_xor_sync(0xffffffffu, mx1, off);
        so = __shfl_xor_sync(0xffffffffu, S1, off);
        nm = fmaxf(mx1, mo);
        S1 = S1 * __expf(mx1 - nm) + so * __expf(mo - nm);
        mx1 = nm;
    }
    float inv0 = 1.f / S0, inv1 = 1.f / S1;

    // ================= Pass 2: normalize + PV (packed even/odd) =========
    ull op0[DK], op1[DK];
#pragma unroll
    for (int d = 0; d < DK; d++) { op0[d] = 0ull; op1[d] = 0ull; }

    {
        float4 pf[4];
        LOADT(pf, vb, 0);
        STORET(pf, 0);
        __syncthreads();
    }
    for (int t = 0; t < NT; t++) {
        float4 pf[4];
        if (t + 1 < NT) { LOADT(pf, vb, t + 1); }
        int bb = t & 1;

#pragma unroll
        for (int c = 0; c < 2; c++) {
            int mm = c * 128 + 4 * l;
            int mg = t * TMA + mm;

            float4 r0 = *(const float4*)(scorep + ar0 + mg);
            float4 r1 = *(const float4*)(scorep + ar1 + mg);

            float p00 = __expf(r0.x - mx0) * inv0;
            float p01 = __expf(r0.y - mx0) * inv0;
            float p02 = __expf(r0.z - mx0) * inv0;
            float p03 = __expf(r0.w - mx0) * inv0;
            float p10 = __expf(r1.x - mx1) * inv1;
            float p11 = __expf(r1.y - mx1) * inv1;
            float p12 = __expf(r1.z - mx1) * inv1;
            float p13 = __expf(r1.w - mx1) * inv1;

            *(float4*)(scorep + ar0 + mg) = make_float4(p00, p01, p02, p03);
            *(float4*)(scorep + ar1 + mg) = make_float4(p10, p11, p12, p13);

            ull pe0 = pk2(p00, p01), po0 = pk2(p02, p03);
            ull pe1 = pk2(p10, p11), po1 = pk2(p12, p13);

#pragma unroll
            for (int d = 0; d < DK; d++) {
                ulonglong2 kk = *(const ulonglong2*)&ts[bb][d][mm];  // (v0,v1),(v2,v3)
                ffma2(op0[d], pe0, kk.x); ffma2(op0[d], po0, kk.y);
                ffma2(op1[d], pe1, kk.x); ffma2(op1[d], po1, kk.y);
            }
        }

        if (t + 1 < NT) { STORET(pf, bb ^ 1); }
        __syncthreads();
    }

    // collapse even/odd halves, then butterfly reduce across lanes
    float o0[DK], o1[DK];
#pragma unroll
    for (int d = 0; d < DK; d++) {
        float2 e0 = upk(op0[d]); o0[d] = e0.x + e0.y;
        float2 e1 = upk(op1[d]); o1[d] = e1.x + e1.y;
    }
#pragma unroll
    for (int off = 16; off; off >>= 1) {
#pragma unroll
        for (int d = 0; d < DK; d++) {
            o0[d] += __shfl_xor_sync(0xffffffffu, o0[d], off);
            o1[d] += __shfl_xor_sync(0xffffffffu, o1[d], off);
        }
    }

    // out layout: out[(b*N+n)*128 + d*8 + h]
    if (outp) {
        if (l == 0) {
            float* ob = outp + ((size_t)b * NN + n0) * DOUT + h;
#pragma unroll
            for (int d = 0; d < DK; d++) ob[(size_t)d * H] = o0[d];
        } else if (l == 1) {
            float* ob = outp + ((size_t)b * NN + n1) * DOUT + h;
#pragma unroll
            for (int d = 0; d < DK; d++) ob[(size_t)d * H] = o1[d];
        }
    }
}

// ============================================================
extern "C" void kernel_launch(void* const* d_in, const int* in_sizes, int n_in,
                              void* d_out, int out_size) {
    const float* x   = (const float*)d_in[0];
    const int*   adj = (const int*)  d_in[1];
    const float* sp  = (const float*)d_in[2];
    const float* Wq  = (const float*)d_in[3];
    const float* bq  = (const float*)d_in[4];
    const float* Wk  = (const float*)d_in[5];
    const float* bk  = (const float*)d_in[6];
    const float* Wv  = (const float*)d_in[7];
    const float* bv  = (const float*)d_in[8];

    const long long OUT_ELEMS  = (long long)BS * NN * DOUT;              // 524288
    const long long ATTN_ELEMS = (long long)BS * H * NN * (long long)NN; // 67108864

    float* base  = (float*)d_out;
    float* outp  = nullptr;
    float* attnp = nullptr;
    long long osz = (long long)out_size;
    if (osz >= OUT_ELEMS + ATTN_ELEMS) { outp = base; attnp = base + OUT_ELEMS; }
    else if (osz == ATTN_ELEMS)        { attnp = base; }
    else                               { outp = base; }

    float* scorep = attnp ? attnp : base;

    dim3 pgrid(BS * NN / PBM, 3);
    proj_kernel<<<pgrid, 256>>>(x, Wq, bq, Wk, bk, Wv, bv);

    dim3 agrid(NN / ROWS_PB, H, BS);
    attn_kernel<<<agrid, 256>>>(sp, adj, outp, scorep);
}

// round 16
// speedup vs baseline: 1.2914x; 1.0657x over previous
#include <cuda_runtime.h>

typedef unsigned long long ull;

#define BS 2
#define NN 2048
#define DIN 128
#define DOUT 128
#define H 8
#define DK 16

#define TMA 256
#define NT (NN / TMA)       // 8 tiles
#define STRD (TMA + 4)      // 260: STRD mod 32 == 4 (needed by swizzle proof)

// xor swizzle on m-index: multiples of 8 words, preserves 16B blocks
#define SW(d) (((d) >> 2) << 3)

// -------- scratch (no allocs allowed) --------
__device__ float g_Q[(size_t)BS*H*NN*DK];
__device__ float g_K[(size_t)BS*H*NN*DK];
__device__ float g_V[(size_t)BS*H*NN*DK];

// ---------- f32x2 helpers ----------
__device__ __forceinline__ void ffma2(ull& d, ull a, ull b) {
    asm("fma.rn.f32x2 %0, %1, %2, %0;" : "+l"(d) : "l"(a), "l"(b));
}
__device__ __forceinline__ ull pk2(float a, float b) {
    ull r; asm("mov.b64 %0, {%1, %2};" : "=l"(r) : "f"(a), "f"(b)); return r;
}
__device__ __forceinline__ float2 upk(ull v) {
    float2 r; asm("mov.b64 {%0, %1}, %2;" : "=f"(r.x), "=f"(r.y) : "l"(v)); return r;
}

// ============================================================
// Projection: y = X @ W^T + b, written as [b][h][n][dk]
// PBM=32 -> grid 384 (balanced over 148 SMs)
// ============================================================
#define PBM 32
__global__ __launch_bounds__(256, 2) void proj_kernel(
    const float* __restrict__ X,
    const float* __restrict__ Wq, const float* __restrict__ bq,
    const float* __restrict__ Wk, const float* __restrict__ bk,
    const float* __restrict__ Wv, const float* __restrict__ bv)
{
    __shared__ float Xs[PBM][33];
    __shared__ float Wt[32][128];

    int tid = threadIdx.x;
    int sel = blockIdx.y;
    const float* W    = (sel == 0) ? Wq : ((sel == 1) ? Wk : Wv);
    const float* bias = (sel == 0) ? bq : ((sel == 1) ? bk : bv);
    float* dst        = (sel == 0) ? g_Q : ((sel == 1) ? g_K : g_V);

    int tx = tid & 63;
    int ty = tid >> 6;          // 0..3 -> rows ty*8 .. ty*8+7
    int row0 = blockIdx.x * PBM;

    float acc0[8], acc1[8];
#pragma unroll
    for (int i = 0; i < 8; i++) { acc0[i] = 0.f; acc1[i] = 0.f; }

    for (int k0 = 0; k0 < DIN; k0 += 32) {
        __syncthreads();
        // stage X tile 32x32 (256 float4, one per thread)
        {
            int xr = tid >> 3;
            int xc = (tid & 7) << 2;
            float4 xv = *(const float4*)(X + (size_t)(row0 + xr) * DIN + k0 + xc);
            Xs[xr][xc + 0] = xv.x; Xs[xr][xc + 1] = xv.y;
            Xs[xr][xc + 2] = xv.z; Xs[xr][xc + 3] = xv.w;
        }
        // stage W^T tile 32x128
#pragma unroll
        for (int r = 0; r < 4; r++) {
            int i = tid + 256 * r;
            int o  = i >> 3;
            int kc = (i & 7) << 2;
            float4 wv = *(const float4*)(W + (size_t)o * DIN + k0 + kc);
            Wt[kc + 0][o] = wv.x; Wt[kc + 1][o] = wv.y;
            Wt[kc + 2][o] = wv.z; Wt[kc + 3][o] = wv.w;
        }
        __syncthreads();
#pragma unroll
        for (int kk = 0; kk < 32; kk++) {
            float w0 = Wt[kk][tx];
            float w1 = Wt[kk][tx + 64];
#pragma unroll
            for (int rr = 0; rr < 8; rr++) {
                float xv = Xs[ty * 8 + rr][kk];
                acc0[rr] = fmaf(xv, w0, acc0[rr]);
                acc1[rr] = fmaf(xv, w1, acc1[rr]);
            }
        }
    }

    float b0 = bias[tx], b1 = bias[tx + 64];
    int c0 = tx, c1 = tx + 64;
#pragma unroll
    for (int rr = 0; rr < 8; rr++) {
        int grow = row0 + ty * 8 + rr;
        int b = grow / NN, n = grow % NN;
        dst[(((size_t)b * H + (c0 >> 4)) * NN + n) * DK + (c0 & 15)] = acc0[rr] + b0;
        dst[(((size_t)b * H + (c1 >> 4)) * NN + n) * DK + (c1 & 15)] = acc1[rr] + b1;
    }
}

// ============================================================
// Fused attention (R15 + conflict-free swizzled staging):
// Pass 1: QK (f32x2 m-packed) + bias + mask -> RAW scores, online stats.
// Pass 2: LDG raw scores, p = exp(s-mx)*inv, overwrite p, packed PV.
// Double-buffered tiles, one __syncthreads per tile, XOR-swizzled
// [d][m^SW(d)] layout -> conflict-free STS and LDS.
// grid (128,8,2), block 256.
// ============================================================
#define ROWS_PB 16

__global__ __launch_bounds__(256, 2) void attn_kernel(
    const float* __restrict__ sp, const int* __restrict__ adj,
    float* __restrict__ outp, float* __restrict__ scorep)
{
    __shared__ float ts[2][DK][STRD];   // double-buffered swizzled tiles

    int tid = threadIdx.x;
    int w = tid >> 5;
    int l = tid & 31;
    int h = blockIdx.y, b = blockIdx.z;
    int bh = b * H + h;
    int n0 = blockIdx.x * ROWS_PB + w * 2;
    int n1 = n0 + 1;

    const float* kb = g_K + (size_t)bh * NN * DK;
    const float* vb = g_V + (size_t)bh * NN * DK;

    size_t ar0 = ((size_t)bh * NN + n0) * NN;
    size_t ar1 = ((size_t)bh * NN + n1) * NN;

    // staging indices (constant per thread)
    int sm0 = tid >> 2;                 // m base
    int sdg = (tid & 3) << 2;           // d-group

    // q dup packs (q[d], q[d]) pre-scaled by 1/sqrt(DK)=0.25
    ull qq0[DK], qq1[DK];
    {
        const float* qr0 = g_Q + ((size_t)bh * NN + n0) * DK;
        const float* qr1 = g_Q + ((size_t)bh * NN + n1) * DK;
#pragma unroll
        for (int d = 0; d < DK; d++) {
            float v0 = qr0[d] * 0.25f;
            float v1 = qr1[d] * 0.25f;
            qq0[d] = pk2(v0, v0);
            qq1[d] = pk2(v1, v1);
        }
    }

    const float* sp0 = sp + (size_t)n0 * NN;
    const float* sp1 = sp + (size_t)n1 * NN;
    const int* ad0 = adj + ((size_t)b * NN + n0) * NN;
    const int* ad1 = adj + ((size_t)b * NN + n1) * NN;

    float mx0 = -3.0e38f, mx1 = -3.0e38f, S0 = 0.f, S1 = 0.f;

    // ---- staging helpers (4 float4 per thread per tile, swizzled STS) ----
#define LOADT(pf, srcbase, t)                                               \
    _Pragma("unroll")                                                       \
    for (int r = 0; r < 4; r++)                                             \
        pf[r] = *(const float4*)((srcbase) +                                \
                 ((size_t)((t) * TMA + sm0 + 64 * r)) * DK + sdg);

#define STORET(pf, bb)                                                      \
    _Pragma("unroll")                                                       \
    for (int r = 0; r < 4; r++) {                                           \
        int m = sm0 + 64 * r;                                               \
        ts[bb][sdg + 0][m ^ SW(sdg + 0)] = pf[r].x;                         \
        ts[bb][sdg + 1][m ^ SW(sdg + 1)] = pf[r].y;                         \
        ts[bb][sdg + 2][m ^ SW(sdg + 2)] = pf[r].z;                         \
        ts[bb][sdg + 3][m ^ SW(sdg + 3)] = pf[r].w;                         \
    }

    // ================= Pass 1: scores + stats =================
    {
        float4 pf[4];
        LOADT(pf, kb, 0);
        STORET(pf, 0);
        __syncthreads();
    }
    for (int t = 0; t < NT; t++) {
        float4 pf[4];
        if (t + 1 < NT) { LOADT(pf, kb, t + 1); }
        int bb = t & 1;

#pragma unroll
        for (int c = 0; c < 2; c++) {
            int mm = c * 128 + 4 * l;
            int mg = t * TMA + mm;

            ull d0a = 0ull, d0b = 0ull, d1a = 0ull, d1b = 0ull;
#pragma unroll
            for (int d = 0; d < DK; d++) {
                ulonglong2 kk = *(const ulonglong2*)&ts[bb][d][mm ^ SW(d)];
                ffma2(d0a, qq0[d], kk.x); ffma2(d0b, qq0[d], kk.y);
                ffma2(d1a, qq1[d], kk.x); ffma2(d1b, qq1[d], kk.y);
            }
            float2 u0a = upk(d0a), u0b = upk(d0b), u1a = upk(d1a), u1b = upk(d1b);

            float4 sv0 = *(const float4*)(sp0 + mg);
            float4 sv1 = *(const float4*)(sp1 + mg);
            int4 a0 = *(const int4*)(ad0 + mg);
            int4 a1 = *(const int4*)(ad1 + mg);

            sv0.x = (mg + 0 == n0) ? 0.f : sv0.x;
            sv0.y = (mg + 1 == n0) ? 0.f : sv0.y;
            sv0.z = (mg + 2 == n0) ? 0.f : sv0.z;
            sv0.w = (mg + 3 == n0) ? 0.f : sv0.w;
            sv1.x = (mg + 0 == n1) ? 0.f : sv1.x;
            sv1.y = (mg + 1 == n1) ? 0.f : sv1.y;
            sv1.z = (mg + 2 == n1) ? 0.f : sv1.z;
            sv1.w = (mg + 3 == n1) ? 0.f : sv1.w;

            float s00 = a0.x ? (u0a.x + sv0.x) : -1e10f;
            float s01 = a0.y ? (u0a.y + sv0.y) : -1e10f;
            float s02 = a0.z ? (u0b.x + sv0.z) : -1e10f;
            float s03 = a0.w ? (u0b.y + sv0.w) : -1e10f;
            float s10 = a1.x ? (u1a.x + sv1.x) : -1e10f;
            float s11 = a1.y ? (u1a.y + sv1.y) : -1e10f;
            float s12 = a1.z ? (u1b.x + sv1.z) : -1e10f;
            float s13 = a1.w ? (u1b.y + sv1.w) : -1e10f;

            *(float4*)(scorep + ar0 + mg) = make_float4(s00, s01, s02, s03);
            *(float4*)(scorep + ar1 + mg) = make_float4(s10, s11, s12, s13);

            float cm0 = fmaxf(fmaxf(s00, s01), fmaxf(s02, s03));
            float nm0 = fmaxf(mx0, cm0);
            S0 = S0 * __expf(mx0 - nm0)
               + __expf(s00 - nm0) + __expf(s01 - nm0)
               + __expf(s02 - nm0) + __expf(s03 - nm0);
            mx0 = nm0;

            float cm1 = fmaxf(fmaxf(s10, s11), fmaxf(s12, s13));
            float nm1 = fmaxf(mx1, cm1);
            S1 = S1 * __expf(mx1 - nm1)
               + __expf(s10 - nm1) + __expf(s11 - nm1)
               + __expf(s12 - nm1) + __expf(s13 - nm1);
            mx1 = nm1;
        }

        if (t + 1 < NT) { STORET(pf, bb ^ 1); }
        __syncthreads();
    }

    // warp-combine (max,sum) exactly
#pragma unroll
    for (int off = 16; off; off >>= 1) {
        float mo = __shfl_xor_sync(0xffffffffu, mx0, off);
        float so = __shfl_xor_sync(0xffffffffu, S0, off);
        float nm = fmaxf(mx0, mo);
        S0 = S0 * __expf(mx0 - nm) + so * __expf(mo - nm);
        mx0 = nm;
        mo = __shfl_xor_sync(0xffffffffu, mx1, off);
        so = __shfl_xor_sync(0xffffffffu, S1, off);
        nm = fmaxf(mx1, mo);
        S1 = S1 * __expf(mx1 - nm) + so * __expf(mo - nm);
        mx1 = nm;
    }
    float inv0 = 1.f / S0, inv1 = 1.f / S1;

    // ================= Pass 2: normalize + PV (packed even/odd) =========
    ull op0[DK], op1[DK];
#pragma unroll
    for (int d = 0; d < DK; d++) { op0[d] = 0ull; op1[d] = 0ull; }

    {
        float4 pf[4];
        LOADT(pf, vb, 0);
        STORET(pf, 0);
        __syncthreads();
    }
    for (int t = 0; t < NT; t++) {
        float4 pf[4];
        if (t + 1 < NT) { LOADT(pf, vb, t + 1); }
        int bb = t & 1;

#pragma unroll
        for (int c = 0; c < 2; c++) {
            int mm = c * 128 + 4 * l;
            int mg = t * TMA + mm;

            float4 r0 = *(const float4*)(scorep + ar0 + mg);
            float4 r1 = *(const float4*)(scorep + ar1 + mg);

            float p00 = __expf(r0.x - mx0) * inv0;
            float p01 = __expf(r0.y - mx0) * inv0;
            float p02 = __expf(r0.z - mx0) * inv0;
            float p03 = __expf(r0.w - mx0) * inv0;
            float p10 = __expf(r1.x - mx1) * inv1;
            float p11 = __expf(r1.y - mx1) * inv1;
            float p12 = __expf(r1.z - mx1) * inv1;
            float p13 = __expf(r1.w - mx1) * inv1;

            *(float4*)(scorep + ar0 + mg) = make_float4(p00, p01, p02, p03);
            *(float4*)(scorep + ar1 + mg) = make_float4(p10, p11, p12, p13);

            ull pe0 = pk2(p00, p01), po0 = pk2(p02, p03);
            ull pe1 = pk2(p10, p11), po1 = pk2(p12, p13);

#pragma unroll
            for (int d = 0; d < DK; d++) {
                ulonglong2 kk = *(const ulonglong2*)&ts[bb][d][mm ^ SW(d)];
                ffma2(op0[d], pe0, kk.x); ffma2(op0[d], po0, kk.y);
                ffma2(op1[d], pe1, kk.x); ffma2(op1[d], po1, kk.y);
            }
        }

        if (t + 1 < NT) { STORET(pf, bb ^ 1); }
        __syncthreads();
    }

    // collapse even/odd halves, then butterfly reduce across lanes
    float o0[DK], o1[DK];
#pragma unroll
    for (int d = 0; d < DK; d++) {
        float2 e0 = upk(op0[d]); o0[d] = e0.x + e0.y;
        float2 e1 = upk(op1[d]); o1[d] = e1.x + e1.y;
    }
#pragma unroll
    for (int off = 16; off; off >>= 1) {
#pragma unroll
        for (int d = 0; d < DK; d++) {
            o0[d] += __shfl_xor_sync(0xffffffffu, o0[d], off);
            o1[d] += __shfl_xor_sync(0xffffffffu, o1[d], off);
        }
    }

    // out layout: out[(b*N+n)*128 + d*8 + h]
    if (outp) {
        if (l == 0) {
            float* ob = outp + ((size_t)b * NN + n0) * DOUT + h;
#pragma unroll
            for (int d = 0; d < DK; d++) ob[(size_t)d * H] = o0[d];
        } else if (l == 1) {
            float* ob = outp + ((size_t)b * NN + n1) * DOUT + h;
#pragma unroll
            for (int d = 0; d < DK; d++) ob[(size_t)d * H] = o1[d];
        }
    }
}

// ============================================================
extern "C" void kernel_launch(void* const* d_in, const int* in_sizes, int n_in,
                              void* d_out, int out_size) {
    const float* x   = (const float*)d_in[0];
    const int*   adj = (const int*)  d_in[1];
    const float* sp  = (const float*)d_in[2];
    const float* Wq  = (const float*)d_in[3];
    const float* bq  = (const float*)d_in[4];
    const float* Wk  = (const float*)d_in[5];
    const float* bk  = (const float*)d_in[6];
    const float* Wv  = (const float*)d_in[7];
    const float* bv  = (const float*)d_in[8];

    const long long OUT_ELEMS  = (long long)BS * NN * DOUT;              // 524288
    const long long ATTN_ELEMS = (long long)BS * H * NN * (long long)NN; // 67108864

    float* base  = (float*)d_out;
    float* outp  = nullptr;
    float* attnp = nullptr;
    long long osz = (long long)out_size;
    if (osz >= OUT_ELEMS + ATTN_ELEMS) { outp = base; attnp = base + OUT_ELEMS; }
    else if (osz == ATTN_ELEMS)        { attnp = base; }
    else                               { outp = base; }

    float* scorep = attnp ? attnp : base;

    dim3 pgrid(BS * NN / PBM, 3);
    proj_kernel<<<pgrid, 256>>>(x, Wq, bq, Wk, bk, Wv, bv);

    dim3 agrid(NN / ROWS_PB, H, BS);
    attn_kernel<<<agrid, 256>>>(sp, adj, outp, scorep);
}